// round 15
// baseline (speedup 1.0000x reference)
#include <cuda_runtime.h>
#include <cstdint>

// DTW wavefront, warp-specialized, 16 CTAs (one per SM), 8-step supersteps.
// Intra-warp left/diag handoff via shfl_up (registers), NOT smem — removes the
// store->load serialization from the loop-carried path. Only remaining serial
// dependence is the per-column FMNMX chain (4 cyc/row).
// Warp 0 = DP. Warp 1 = helper (d^2 prefix sums, S ring depth 32).
// Warp 2 = import (neighbor boundary batches). Warp 3 = export.

#define KLEN   512
#define RR     16
#define NCTA   16
#define NB     4096            // 65536 / 16
#define NSP    4128            // padded step count (mult of 8), real = 4127
#define GB     8
#define NBATCH (NB / GB)       // 512

#define SR_LS  516             // 32 slots * 16 + 4 pad per lane (conflict-free)

__device__ float    g_bnd[NCTA][NB][16];
__device__ unsigned g_flag[NCTA];

__device__ __forceinline__ unsigned ld_acq_g(const unsigned* p) {
    unsigned v;
    asm volatile("ld.global.acquire.gpu.b32 %0, [%1];" : "=r"(v) : "l"(p));
    return v;
}
__device__ __forceinline__ void st_rel_g(unsigned* p, unsigned v) {
    asm volatile("st.global.release.gpu.b32 [%0], %1;" :: "l"(p), "r"(v));
}
__device__ __forceinline__ unsigned sld_acq(const unsigned* p) {
    unsigned a = (unsigned)__cvta_generic_to_shared((void*)p);
    unsigned v;
    asm volatile("ld.acquire.cta.shared.b32 %0, [%1];" : "=r"(v) : "r"(a));
    return v;
}
__device__ __forceinline__ void sst_rel(unsigned* p, unsigned v) {
    unsigned a = (unsigned)__cvta_generic_to_shared((void*)p);
    asm volatile("st.release.cta.shared.b32 [%0], %1;" :: "r"(a), "r"(v));
}

__global__ void __launch_bounds__(128, 1)
dtw_ws5_kernel(const float* __restrict__ x,
               const float* __restrict__ ker,
               float* __restrict__ out)
{
    __shared__ __align__(16) float sm_S[32 * SR_LS];     // 64.5 KB S ring
    __shared__ __align__(16) float sm_bnd[32 * 16];      // 2 KB neighbor boundary ring
    __shared__ __align__(16) float sm_exp[32 * 16];      // 2 KB export ring
    __shared__ unsigned sm_hctr, sm_bctr, sm_ectr, sm_dpc;

    const int w    = blockIdx.x;
    const int tid  = threadIdx.x;
    const int wid  = tid >> 5;
    const int lane = tid & 31;
    const float INFV = __int_as_float(0x7f800000);

    if (tid == 0) {
        sm_hctr = 0; sm_ectr = 0; sm_dpc = 0;
        sm_bctr = (w == 0) ? 0x7ffffff0u : 0u;
    }
    for (int i = tid; i < 32 * 16; i += 128) sm_bnd[i] = INFV;
    __syncthreads();

    if (wid == 0) {
        // ========================= DP warp =========================
        const bool col0  = (w == 0) && (lane == 0);
        const bool lastl = (lane == 31);
        float uc = col0 ? 0.0f : INFV;
        float dc = INFV;
        float ac[16];
        #pragma unroll
        for (int r = 0; r < 16; ++r) ac[r] = INFV;
        int hc = 0, bc = (w == 0) ? 0x7ffffff0 : 0, ec = 0;

        // One wavefront step. left comes from shfl of previous-step ac.
        #define DP_STEP(kk, RESET)                                             \
        {                                                                      \
            const int k = (kk);                                                \
            const int b = s0 + k - lane;                                       \
            float left[16];                                                    \
            _Pragma("unroll")                                                  \
            for (int r = 0; r < 16; ++r)                                       \
                left[r] = __shfl_up_sync(0xffffffffu, ac[r], 1);               \
            if (lane == 0) {                                                   \
                const float* bp = &sm_bnd[(bOff + k) << 4];                    \
                float4 B0 = *(const float4*)(bp + 0);                          \
                float4 B1 = *(const float4*)(bp + 4);                          \
                float4 B2 = *(const float4*)(bp + 8);                          \
                float4 B3 = *(const float4*)(bp + 12);                         \
                left[0]=B0.x;  left[1]=B0.y;  left[2]=B0.z;  left[3]=B0.w;     \
                left[4]=B1.x;  left[5]=B1.y;  left[6]=B1.z;  left[7]=B1.w;     \
                left[8]=B2.x;  left[9]=B2.y;  left[10]=B2.z; left[11]=B2.w;    \
                left[12]=B3.x; left[13]=B3.y; left[14]=B3.z; left[15]=B3.w;    \
            }                                                                  \
            const float* sp = &sm_S[lane * SR_LS + (((sB + k) & 31) << 4)];    \
            float4 P0 = *(const float4*)(sp + 0);                              \
            float4 P1 = *(const float4*)(sp + 4);                              \
            float4 P2 = *(const float4*)(sp + 8);                              \
            float4 P3 = *(const float4*)(sp + 12);                             \
            float S[16] = {P0.x,P0.y,P0.z,P0.w, P1.x,P1.y,P1.z,P1.w,           \
                           P2.x,P2.y,P2.z,P2.w, P3.x,P3.y,P3.z,P3.w};          \
            if (RESET && b == 0) { uc = col0 ? 0.0f : INFV; dc = INFV; }       \
            float m = uc, prev = dc;                                           \
            _Pragma("unroll")                                                  \
            for (int r = 0; r < 16; ++r) {                                     \
                float e = fminf(prev, left[r]);                                \
                float t = (r == 0) ? e : (e - S[r - 1]);                       \
                m = fminf(m, t);                                               \
                ac[r] = m + S[r];                                              \
                prev = left[r];                                                \
            }                                                                  \
            uc = ac[15]; dc = left[15];                                        \
            if (lastl && (unsigned)b < (unsigned)NB) {                         \
                float* ep = &sm_exp[((eB + k) & 31) << 4];                     \
                *(float4*)(ep + 0)  = make_float4(ac[0],  ac[1],  ac[2],  ac[3]);  \
                *(float4*)(ep + 4)  = make_float4(ac[4],  ac[5],  ac[6],  ac[7]);  \
                *(float4*)(ep + 8)  = make_float4(ac[8],  ac[9],  ac[10], ac[11]); \
                *(float4*)(ep + 12) = make_float4(ac[12], ac[13], ac[14], ac[15]); \
            }                                                                  \
        }

        #define DP_SUPER(RESET)                                                \
        {                                                                      \
            if (lastl) sst_rel(&sm_dpc, (unsigned)s0);                         \
            if (hc < s0 + 8) { do { hc = (int)sld_acq(&sm_hctr); } while (hc < s0 + 8); } \
            if (bc < s0 + 8) { do { bc = (int)sld_acq(&sm_bctr); } while (bc < s0 + 8); } \
            if (ec < s0 - 48) { do { ec = (int)sld_acq(&sm_ectr); } while (ec < s0 - 48); } \
            const int bOff = s0 & 31;                                          \
            const int eB   = (s0 + 1) & 31;                                    \
            const int sB   = (s0 - lane) & 31;                                 \
            DP_STEP(0, RESET) DP_STEP(1, RESET) DP_STEP(2, RESET)              \
            DP_STEP(3, RESET) DP_STEP(4, RESET) DP_STEP(5, RESET)              \
            DP_STEP(6, RESET) DP_STEP(7, RESET)                                \
        }

        // fill supersteps (carry resets possible: b==0 occurs at s<32)
        for (int s0 = 0; s0 < 32; s0 += 8) DP_SUPER(true)
        // steady + drain
        for (int s0 = 32; s0 < NSP; s0 += 8) DP_SUPER(false)

        #undef DP_SUPER
        #undef DP_STEP
        if (lastl) sst_rel(&sm_dpc, (unsigned)(NSP + 64));
    }
    else if (wid == 1) {
        // ========================= helper warp =========================
        const float kj = __ldg(&ker[(w << 5) + lane]);
        int dpc = 0;
        for (int t0 = 0; t0 < NSP; t0 += 8) {
            if (lane == 0) sst_rel(&sm_hctr, (unsigned)t0);
            if (dpc < t0 - 24) { do { dpc = (int)sld_acq(&sm_dpc); } while (dpc < t0 - 24); }
            #pragma unroll
            for (int k = 0; k < 8; ++k) {
                const int h = t0 + k - lane;
                if ((unsigned)h < (unsigned)NB) {
                    const float4* xp = (const float4*)(x + h * RR);
                    float4 a = __ldg(xp + 0), b4 = __ldg(xp + 1);
                    float4 c = __ldg(xp + 2), d4 = __ldg(xp + 3);
                    float xv[16] = {a.x,a.y,a.z,a.w, b4.x,b4.y,b4.z,b4.w,
                                    c.x,c.y,c.z,c.w, d4.x,d4.y,d4.z,d4.w};
                    float S[16];
                    float d0 = kj - xv[0];
                    S[0] = d0 * d0;
                    #pragma unroll
                    for (int r = 1; r < 16; ++r) {
                        float d = kj - xv[r];
                        S[r] = fmaf(d, d, S[r - 1]);
                    }
                    float* sp = &sm_S[lane * SR_LS + ((h & 31) << 4)];
                    *(float4*)(sp + 0)  = make_float4(S[0],  S[1],  S[2],  S[3]);
                    *(float4*)(sp + 4)  = make_float4(S[4],  S[5],  S[6],  S[7]);
                    *(float4*)(sp + 8)  = make_float4(S[8],  S[9],  S[10], S[11]);
                    *(float4*)(sp + 12) = make_float4(S[12], S[13], S[14], S[15]);
                }
            }
        }
        if (lane == 0) sst_rel(&sm_hctr, (unsigned)(NSP + 64));
    }
    else if (wid == 2) {
        // ========================= import warp =========================
        if (w > 0) {
            int dpc = 0;
            unsigned gf = 0;
            for (int kk = 0; kk < NBATCH; ++kk) {
                const int n0 = kk * GB;
                if (dpc < n0 - 24) { do { dpc = (int)sld_acq(&sm_dpc); } while (dpc < n0 - 24); }
                const unsigned need = (unsigned)(n0 + GB);
                while (gf < need) {
                    gf = ld_acq_g(&g_flag[w - 1]);
                    if (gf < need) __nanosleep(64);
                }
                float4 v = __ldcg((const float4*)&g_bnd[w - 1][n0][0] + lane);
                *((float4*)&sm_bnd[(n0 & 31) << 4] + lane) = v;
                __syncwarp();
                if (lane == 0) sst_rel(&sm_bctr, (unsigned)(n0 + GB));
            }
            if (lane == 0) sst_rel(&sm_bctr, 0x7ffffff0u);
        }
    }
    else {
        // ========================= export warp =========================
        int dpc = 0;
        for (int kk = 0; kk < NBATCH; ++kk) {
            const int b0 = kk * GB;
            const int need = b0 + 40;          // lane31 done block b0+7 at step b0+38
            if (dpc < need) { do { dpc = (int)sld_acq(&sm_dpc); } while (dpc < need); }
            float4 v = *((const float4*)&sm_exp[(b0 & 31) << 4] + lane);
            if (w == NCTA - 1) {
                ((float4*)(out + (b0 << 4)))[lane] = v;
            } else {
                __stcg((float4*)&g_bnd[w][b0][0] + lane, v);
            }
            __syncwarp();
            if (lane == 0) {
                if (w < NCTA - 1) st_rel_g(&g_flag[w], (unsigned)(b0 + GB));
                sst_rel(&sm_ectr, (unsigned)(b0 + GB));
            }
        }
    }
}

extern "C" void kernel_launch(void* const* d_in, const int* in_sizes, int n_in,
                              void* d_out, int out_size)
{
    const float* x;
    const float* ker;
    if (n_in >= 2 && in_sizes[0] == KLEN && in_sizes[1] != KLEN) {
        ker = (const float*)d_in[0];
        x   = (const float*)d_in[1];
    } else {
        x   = (const float*)d_in[0];
        ker = (const float*)d_in[1];
    }
    float* out = (float*)d_out;

    dtw_ws5_kernel<<<NCTA, 128>>>(x, ker, out);
}